// round 7
// baseline (speedup 1.0000x reference)
#include <cuda_runtime.h>
#include <cuda_bf16.h>
#include <cstdint>

#define BB   16
#define SS   1024
#define DD   1024
#define DHH  4096
#define MROWS (BB * SS)   // 16384

typedef __nv_bfloat16 bf16;

// ---------------------------------------------------------------------------
// Scratch (__device__ globals; no allocation allowed). ~1 GB total.
// ---------------------------------------------------------------------------
__device__ __align__(16) bf16 g_big_hi[MROWS * DHH];
__device__ __align__(16) bf16 g_big_lo[MROWS * DHH];
__device__ __align__(16) bf16 g_a_hi[MROWS * DD];
__device__ __align__(16) bf16 g_a_lo[MROWS * DD];
__device__ __align__(16) bf16 g_b_hi[MROWS * DD];
__device__ __align__(16) bf16 g_b_lo[MROWS * DD];
__device__ __align__(16) bf16 g_q_hi[MROWS * DD];
__device__ __align__(16) bf16 g_q_lo[MROWS * DD];
__device__ __align__(16) bf16 g_k_hi[MROWS * DD];
__device__ __align__(16) bf16 g_k_lo[MROWS * DD];
__device__ __align__(16) bf16 g_vt_hi[MROWS * DD];
__device__ __align__(16) bf16 g_vt_lo[MROWS * DD];
__device__ __align__(16) float g_f0[MROWS * DD];
__device__ __align__(16) float g_f1[MROWS * DD];
__device__ __align__(16) float g_f2[MROWS * DD];
__device__ __align__(16) float g_f3[MROWS * DD];
__device__ __align__(16) float g_f4[MROWS * DD];
__device__ __align__(16) bf16 g_wmlp_hi[DHH * DD];  __device__ __align__(16) bf16 g_wmlp_lo[DHH * DD];
__device__ __align__(16) bf16 g_wproj_hi[DD * DHH]; __device__ __align__(16) bf16 g_wproj_lo[DD * DHH];
__device__ __align__(16) bf16 g_wq_hi[DD * DD];     __device__ __align__(16) bf16 g_wq_lo[DD * DD];
__device__ __align__(16) bf16 g_wk_hi[DD * DD];     __device__ __align__(16) bf16 g_wk_lo[DD * DD];
__device__ __align__(16) bf16 g_wv_hi[DD * DD];     __device__ __align__(16) bf16 g_wv_lo[DD * DD];
__device__ __align__(16) bf16 g_wf1_hi[4*DD * DD];  __device__ __align__(16) bf16 g_wf1_lo[4*DD * DD];
__device__ __align__(16) bf16 g_wf2_hi[DD * 4*DD];  __device__ __align__(16) bf16 g_wf2_lo[DD * 4*DD];

// ---------------------------------------------------------------------------
// PTX helpers (sm_100 base ISA only: cp.async, ldmatrix, mma.sync)
// ---------------------------------------------------------------------------
__device__ __forceinline__ void cp16u(uint32_t sa, const void* g) {
    asm volatile("cp.async.cg.shared.global [%0], [%1], 16;\n" :: "r"(sa), "l"(g));
}
__device__ __forceinline__ void ldm4(uint32_t* r, uint32_t addr) {
    asm volatile("ldmatrix.sync.aligned.m8n8.x4.shared.b16 {%0,%1,%2,%3}, [%4];\n"
                 : "=r"(r[0]), "=r"(r[1]), "=r"(r[2]), "=r"(r[3]) : "r"(addr));
}
__device__ __forceinline__ void mma16816(float* c, const uint32_t* a, const uint32_t* b) {
    asm volatile("mma.sync.aligned.m16n8k16.row.col.f32.bf16.bf16.f32 "
                 "{%0,%1,%2,%3}, {%4,%5,%6,%7}, {%8,%9}, {%0,%1,%2,%3};\n"
                 : "+f"(c[0]), "+f"(c[1]), "+f"(c[2]), "+f"(c[3])
                 : "r"(a[0]), "r"(a[1]), "r"(a[2]), "r"(a[3]), "r"(b[0]), "r"(b[1]));
}
__device__ __forceinline__ void split_bf16(float v, bf16& h, bf16& l) {
    h = __float2bfloat16(v);
    l = __float2bfloat16(v - __bfloat162float(h));
}

// ---------------------------------------------------------------------------
// bf16x3 GEMM: C[M,N] = (Ahi+Alo)[M,K] @ (Bhi+Blo)[N,K]^T (+bias, act)
// CTA tile 128x64, K-tile 32, 256 threads, 2 CTAs/SM, 3-stage cp.async
// pipeline (prefetch 2 ahead, wait_group 1), warp tile 32x32 (4x2 warps).
// Stage layout (rows of GSTRIDE=40 bf16): A-hi[0,128) A-lo[128,256)
// B-hi[256,320) B-lo[320,384). 30720 B/stage, 3 stages = 92160 B.
// OUTM bit0: write fp32 Cf; bit1: write bf16 split Chi/Clo.
// ACT: 0 = none, 1 = relu, 2 = clip(+-100)
// ---------------------------------------------------------------------------
#define GSTRIDE 40
#define KT 32
#define STG_ROWS 384
#define STAGE_BYTES (STG_ROWS * GSTRIDE * 2)    // 30720
#define NSTAGES 3
#define GEMM_SMEM (NSTAGES * STAGE_BYTES)       // 92160

template<int ACT, int OUTM>
__global__ __launch_bounds__(256, 2)
void gemm2(const bf16* __restrict__ Ahi, const bf16* __restrict__ Alo,
           const bf16* __restrict__ Bhi, const bf16* __restrict__ Blo,
           const float* __restrict__ bias,
           float* __restrict__ Cf, bf16* __restrict__ Chi, bf16* __restrict__ Clo,
           int M, int N, int K,
           long long sA, long long sB, long long sC)
{
    extern __shared__ bf16 sm[];
    const int tid = threadIdx.x;
    const int wid = tid >> 5, lane = tid & 31;
    const int wm = wid >> 1, wn = wid & 1;      // 4x2 warps -> 32x32 warp tile
    const long long z = blockIdx.z;
    Ahi += z * sA; Alo += z * sA; Bhi += z * sB; Blo += z * sB;
    const long long bM = (long long)blockIdx.y * 128;
    const long long bN = (long long)blockIdx.x * 64;

    float acc[2][4][4];
    #pragma unroll
    for (int mi = 0; mi < 2; mi++)
        #pragma unroll
        for (int ni = 0; ni < 4; ni++)
            #pragma unroll
            for (int j = 0; j < 4; j++) acc[mi][ni][j] = 0.f;

    const uint32_t smb = (uint32_t)__cvta_generic_to_shared(sm);

    // Column-major chunk mapping: a warp's 32 lanes write 32 distinct rows
    // -> conflict-free STS (stride-40 rows rotate 20 banks/row, distinct per
    // 8-lane phase). Each thread covers one row's full 64B over c=0..3.
    auto load_stage = [&](int s, int k0) {
        const uint32_t base = smb + s * STAGE_BYTES;
        #pragma unroll
        for (int c = 0; c < 4; c++) {
            #pragma unroll
            for (int rr = 0; rr < 2; rr++) {
                const int r = tid + rr * 256;
                if (r < STG_ROWS) {
                    const bf16* gp;
                    if (r < 128)      gp = Ahi + (bM + r)       * (long long)K + k0 + c * 8;
                    else if (r < 256) gp = Alo + (bM + r - 128) * (long long)K + k0 + c * 8;
                    else if (r < 320) gp = Bhi + (bN + r - 256) * (long long)K + k0 + c * 8;
                    else              gp = Blo + (bN + r - 320) * (long long)K + k0 + c * 8;
                    cp16u(base + (uint32_t)(r * (GSTRIDE * 2) + c * 16), gp);
                }
            }
        }
        asm volatile("cp.async.commit_group;\n" ::: "memory");
    };

    auto compute = [&](int s) {
        const uint32_t base = smb + s * STAGE_BYTES;
        #pragma unroll
        for (int ks = 0; ks < 2; ks++) {
            const int lr = lane & 15;
            const int lc = ks * 16 + ((lane >> 4) << 3);
            uint32_t ah[2][4], al[2][4], bh[4][2], bl[4][2];
            #pragma unroll
            for (int mi = 0; mi < 2; mi++) {
                ldm4(ah[mi], base + 2u * ((      wm*32 + mi*16 + lr) * GSTRIDE + lc));
                ldm4(al[mi], base + 2u * ((128 + wm*32 + mi*16 + lr) * GSTRIDE + lc));
            }
            #pragma unroll
            for (int g = 0; g < 2; g++) {
                uint32_t r[4];
                ldm4(r, base + 2u * ((256 + wn*32 + g*16 + lr) * GSTRIDE + lc));
                bh[g*2][0] = r[0]; bh[g*2+1][0] = r[1]; bh[g*2][1] = r[2]; bh[g*2+1][1] = r[3];
                ldm4(r, base + 2u * ((320 + wn*32 + g*16 + lr) * GSTRIDE + lc));
                bl[g*2][0] = r[0]; bl[g*2+1][0] = r[1]; bl[g*2][1] = r[2]; bl[g*2+1][1] = r[3];
            }
            #pragma unroll
            for (int mi = 0; mi < 2; mi++)
                #pragma unroll
                for (int ni = 0; ni < 4; ni++)
                    mma16816(acc[mi][ni], ah[mi], bh[ni]);
            #pragma unroll
            for (int mi = 0; mi < 2; mi++)
                #pragma unroll
                for (int ni = 0; ni < 4; ni++)
                    mma16816(acc[mi][ni], ah[mi], bl[ni]);
            #pragma unroll
            for (int mi = 0; mi < 2; mi++)
                #pragma unroll
                for (int ni = 0; ni < 4; ni++)
                    mma16816(acc[mi][ni], al[mi], bh[ni]);
        }
    };

    const int T = K / KT;
    load_stage(0, 0);
    load_stage(1, KT);
    int sidx = 0;                       // i % 3, tracked incrementally
    for (int i = 0; i < T; i++) {
        if (i == T - 1)
            asm volatile("cp.async.wait_group 0;\n" ::: "memory");
        else
            asm volatile("cp.async.wait_group 1;\n" ::: "memory");
        __syncthreads();
        if (i + 2 < T) {
            int ps = sidx + 2; if (ps >= NSTAGES) ps -= NSTAGES;
            load_stage(ps, (i + 2) * KT);
        }
        compute(sidx);
        if (++sidx == NSTAGES) sidx = 0;
    }

    // epilogue
    const long long cb = z * sC;
    const int g4 = lane >> 2, l4 = lane & 3;
    #pragma unroll
    for (int mi = 0; mi < 2; mi++) {
        #pragma unroll
        for (int half = 0; half < 2; half++) {
            const long long row = bM + wm*32 + mi*16 + half*8 + g4;
            #pragma unroll
            for (int ni = 0; ni < 4; ni++) {
                const long long col = bN + wn*32 + ni*8 + l4*2;
                float v0 = acc[mi][ni][half*2 + 0];
                float v1 = acc[mi][ni][half*2 + 1];
                if (bias) { v0 += bias[col]; v1 += bias[col + 1]; }
                if (ACT == 1) { v0 = fmaxf(v0, 0.f); v1 = fmaxf(v1, 0.f); }
                if (ACT == 2) {
                    v0 = fminf(fmaxf(v0, -100.f), 100.f);
                    v1 = fminf(fmaxf(v1, -100.f), 100.f);
                }
                const long long idx = cb + row * N + col;
                if (OUTM & 1) *(float2*)(Cf + idx) = make_float2(v0, v1);
                if (OUTM & 2) {
                    bf16 h0, l0, h1, l1;
                    split_bf16(v0, h0, l0); split_bf16(v1, h1, l1);
                    *(__nv_bfloat162*)(Chi + idx) = __halves2bfloat162(h0, h1);
                    *(__nv_bfloat162*)(Clo + idx) = __halves2bfloat162(l0, l1);
                }
            }
        }
    }
}

// ---------------------------------------------------------------------------
// Transpose + split: in fp32 [R][C] (batched) -> out bf16 [C][R] hi/lo
// ---------------------------------------------------------------------------
__global__ __launch_bounds__(256)
void tsplit(const float* __restrict__ in, bf16* __restrict__ ohi, bf16* __restrict__ olo,
            int R, int C, long long sIn, long long sOut)
{
    __shared__ float t[32][33];
    in += blockIdx.z * sIn; ohi += blockIdx.z * sOut; olo += blockIdx.z * sOut;
    const int bx = blockIdx.x * 32, by = blockIdx.y * 32;
    const int tx = threadIdx.x & 31, ty = threadIdx.x >> 5;   // 32 x 8
    #pragma unroll
    for (int i = 0; i < 32; i += 8)
        t[ty + i][tx] = in[(long long)(by + ty + i) * C + bx + tx];
    __syncthreads();
    #pragma unroll
    for (int i = 0; i < 32; i += 8) {
        float v = t[tx][ty + i];
        bf16 h, l; split_bf16(v, h, l);
        const long long o = (long long)(bx + ty + i) * R + by + tx;
        ohi[o] = h; olo[o] = l;
    }
}

// ---------------------------------------------------------------------------
// LayerNorm over D=1024 (+optional residual); outputs fp32 and/or bf16 split.
// ---------------------------------------------------------------------------
__global__ __launch_bounds__(256)
void ln_kernel(const float* __restrict__ in, const float* __restrict__ res,
               const float* __restrict__ gam, const float* __restrict__ bet,
               float* __restrict__ outf, bf16* __restrict__ ohi, bf16* __restrict__ olo)
{
    __shared__ float sh[64];
    const long long row = blockIdx.x;
    const int t = threadIdx.x;

    float4 v = ((const float4*)(in + row * DD))[t];
    if (res) {
        float4 r = ((const float4*)(res + row * DD))[t];
        v.x += r.x; v.y += r.y; v.z += r.z; v.w += r.w;
    }
    float s  = v.x + v.y + v.z + v.w;
    float ss = v.x*v.x + v.y*v.y + v.z*v.z + v.w*v.w;
    const int lane = t & 31, wid = t >> 5;
    #pragma unroll
    for (int o = 16; o > 0; o >>= 1) {
        s  += __shfl_down_sync(0xffffffffu, s,  o);
        ss += __shfl_down_sync(0xffffffffu, ss, o);
    }
    if (lane == 0) { sh[wid] = s; sh[32 + wid] = ss; }
    __syncthreads();
    if (t == 0) {
        float ts = 0.f, tss = 0.f;
        #pragma unroll
        for (int i = 0; i < 8; i++) { ts += sh[i]; tss += sh[32 + i]; }
        float mean = ts * (1.f / DD);
        float var  = tss * (1.f / DD) - mean * mean;
        sh[0] = mean; sh[1] = rsqrtf(var + 1e-5f);
    }
    __syncthreads();
    const float mean = sh[0], inv = sh[1];

    float4 g4 = ((const float4*)gam)[t];
    float4 b4 = ((const float4*)bet)[t];
    float4 o;
    o.x = (v.x - mean) * inv * g4.x + b4.x;
    o.y = (v.y - mean) * inv * g4.y + b4.y;
    o.z = (v.z - mean) * inv * g4.z + b4.z;
    o.w = (v.w - mean) * inv * g4.w + b4.w;
    if (outf) ((float4*)(outf + row * DD))[t] = o;
    if (ohi) {
        bf16 h0,l0,h1,l1,h2,l2,h3,l3;
        split_bf16(o.x,h0,l0); split_bf16(o.y,h1,l1);
        split_bf16(o.z,h2,l2); split_bf16(o.w,h3,l3);
        __nv_bfloat162* ph = (__nv_bfloat162*)(ohi + row * DD);
        __nv_bfloat162* pl = (__nv_bfloat162*)(olo + row * DD);
        ph[t*2]   = __halves2bfloat162(h0, h1);
        ph[t*2+1] = __halves2bfloat162(h2, h3);
        pl[t*2]   = __halves2bfloat162(l0, l1);
        pl[t*2+1] = __halves2bfloat162(l2, l3);
    }
}

// ---------------------------------------------------------------------------
// Masked scaled softmax; reads fp32 scores, writes bf16 split probs.
// ---------------------------------------------------------------------------
__global__ __launch_bounds__(256)
void softmax_split(const float* __restrict__ scores, const int* __restrict__ mask,
                   const float* __restrict__ scale,
                   bf16* __restrict__ phi, bf16* __restrict__ plo)
{
    __shared__ float sh[16];
    const long long row = blockIdx.x;
    const int b = (int)(row >> 10);
    const int t = threadIdx.x;

    const float4 vin = ((const float4*)(scores + row * SS))[t];
    const int4 mm = ((const int4*)(mask + (long long)b * SS))[t];
    const float sc = scale[0];

    float4 v;
    v.x = mm.x ? vin.x * sc : -1e9f;
    v.y = mm.y ? vin.y * sc : -1e9f;
    v.z = mm.z ? vin.z * sc : -1e9f;
    v.w = mm.w ? vin.w * sc : -1e9f;

    float mx = fmaxf(fmaxf(v.x, v.y), fmaxf(v.z, v.w));
    const int lane = t & 31, wid = t >> 5;
    #pragma unroll
    for (int o = 16; o > 0; o >>= 1)
        mx = fmaxf(mx, __shfl_down_sync(0xffffffffu, mx, o));
    if (lane == 0) sh[wid] = mx;
    __syncthreads();
    if (t == 0) {
        float m = sh[0];
        #pragma unroll
        for (int i = 1; i < 8; i++) m = fmaxf(m, sh[i]);
        sh[8] = m;
    }
    __syncthreads();
    mx = sh[8];

    float4 e;
    e.x = expf(v.x - mx); e.y = expf(v.y - mx);
    e.z = expf(v.z - mx); e.w = expf(v.w - mx);
    float sum = e.x + e.y + e.z + e.w;
    #pragma unroll
    for (int o = 16; o > 0; o >>= 1)
        sum += __shfl_down_sync(0xffffffffu, sum, o);
    __syncthreads();
    if (lane == 0) sh[wid] = sum;
    __syncthreads();
    if (t == 0) {
        float sv = 0.f;
        #pragma unroll
        for (int i = 0; i < 8; i++) sv += sh[i];
        sh[9] = 1.f / sv;
    }
    __syncthreads();
    const float invs = sh[9];

    e.x *= invs; e.y *= invs; e.z *= invs; e.w *= invs;
    bf16 h0,l0,h1,l1,h2,l2,h3,l3;
    split_bf16(e.x,h0,l0); split_bf16(e.y,h1,l1);
    split_bf16(e.z,h2,l2); split_bf16(e.w,h3,l3);
    __nv_bfloat162* ph = (__nv_bfloat162*)(phi + row * SS);
    __nv_bfloat162* pl = (__nv_bfloat162*)(plo + row * SS);
    ph[t*2]   = __halves2bfloat162(h0, h1);
    ph[t*2+1] = __halves2bfloat162(h2, h3);
    pl[t*2]   = __halves2bfloat162(l0, l1);
    pl[t*2+1] = __halves2bfloat162(l2, l3);
}

// ---------------------------------------------------------------------------
// Launch
// ---------------------------------------------------------------------------
extern "C" void kernel_launch(void* const* d_in, const int* in_sizes, int n_in,
                              void* d_out, int out_size)
{
    const float* x       = (const float*)d_in[0];
    const int*   mask    = (const int*)  d_in[1];
    const float* ln_in_g = (const float*)d_in[2];
    const float* ln_in_b = (const float*)d_in[3];
    const float* W_mlp   = (const float*)d_in[4];
    const float* b_mlp   = (const float*)d_in[5];
    const float* W_proj  = (const float*)d_in[6];
    const float* b_proj  = (const float*)d_in[7];
    const float* scale   = (const float*)d_in[8];
    const float* Wq      = (const float*)d_in[9];
    const float* bq      = (const float*)d_in[10];
    const float* Wk      = (const float*)d_in[11];
    const float* bk      = (const float*)d_in[12];
    const float* Wv      = (const float*)d_in[13];
    const float* bv      = (const float*)d_in[14];
    const float* ln1_g   = (const float*)d_in[15];
    const float* ln1_b   = (const float*)d_in[16];
    const float* W_f1    = (const float*)d_in[17];
    const float* b_f1    = (const float*)d_in[18];
    const float* W_f2    = (const float*)d_in[19];
    const float* b_f2    = (const float*)d_in[20];
    const float* ln2_g   = (const float*)d_in[21];
    const float* ln2_b   = (const float*)d_in[22];
    const float* lno_g   = (const float*)d_in[23];
    const float* lno_b   = (const float*)d_in[24];
    float* out = (float*)d_out;

    bf16 *bigH,*bigL,*aH,*aL,*bH,*bL,*qH,*qL,*kH,*kL,*vtH,*vtL;
    bf16 *wmlpH,*wmlpL,*wprojH,*wprojL,*wqH,*wqL,*wkH,*wkL,*wvH,*wvL,*wf1H,*wf1L,*wf2H,*wf2L;
    float *f0,*f1,*f2,*f3,*f4;
    cudaGetSymbolAddress((void**)&bigH, g_big_hi); cudaGetSymbolAddress((void**)&bigL, g_big_lo);
    cudaGetSymbolAddress((void**)&aH, g_a_hi);     cudaGetSymbolAddress((void**)&aL, g_a_lo);
    cudaGetSymbolAddress((void**)&bH, g_b_hi);     cudaGetSymbolAddress((void**)&bL, g_b_lo);
    cudaGetSymbolAddress((void**)&qH, g_q_hi);     cudaGetSymbolAddress((void**)&qL, g_q_lo);
    cudaGetSymbolAddress((void**)&kH, g_k_hi);     cudaGetSymbolAddress((void**)&kL, g_k_lo);
    cudaGetSymbolAddress((void**)&vtH, g_vt_hi);   cudaGetSymbolAddress((void**)&vtL, g_vt_lo);
    cudaGetSymbolAddress((void**)&wmlpH, g_wmlp_hi);   cudaGetSymbolAddress((void**)&wmlpL, g_wmlp_lo);
    cudaGetSymbolAddress((void**)&wprojH, g_wproj_hi); cudaGetSymbolAddress((void**)&wprojL, g_wproj_lo);
    cudaGetSymbolAddress((void**)&wqH, g_wq_hi);   cudaGetSymbolAddress((void**)&wqL, g_wq_lo);
    cudaGetSymbolAddress((void**)&wkH, g_wk_hi);   cudaGetSymbolAddress((void**)&wkL, g_wk_lo);
    cudaGetSymbolAddress((void**)&wvH, g_wv_hi);   cudaGetSymbolAddress((void**)&wvL, g_wv_lo);
    cudaGetSymbolAddress((void**)&wf1H, g_wf1_hi); cudaGetSymbolAddress((void**)&wf1L, g_wf1_lo);
    cudaGetSymbolAddress((void**)&wf2H, g_wf2_hi); cudaGetSymbolAddress((void**)&wf2L, g_wf2_lo);
    cudaGetSymbolAddress((void**)&f0, g_f0); cudaGetSymbolAddress((void**)&f1, g_f1);
    cudaGetSymbolAddress((void**)&f2, g_f2); cudaGetSymbolAddress((void**)&f3, g_f3);
    cudaGetSymbolAddress((void**)&f4, g_f4);

    cudaFuncSetAttribute(gemm2<0,1>, cudaFuncAttributeMaxDynamicSharedMemorySize, GEMM_SMEM);
    cudaFuncSetAttribute(gemm2<0,2>, cudaFuncAttributeMaxDynamicSharedMemorySize, GEMM_SMEM);
    cudaFuncSetAttribute(gemm2<1,2>, cudaFuncAttributeMaxDynamicSharedMemorySize, GEMM_SMEM);
    cudaFuncSetAttribute(gemm2<2,3>, cudaFuncAttributeMaxDynamicSharedMemorySize, GEMM_SMEM);

    const dim3 blk(256);
    const long long SD = (long long)SS * DD;   // 1M: per-batch stride

    // weight transpose+split: W [K][N] -> [N][K] hi/lo
    tsplit<<<dim3(DHH/32, DD/32, 1), blk>>>(W_mlp, wmlpH, wmlpL, DD, DHH, 0, 0);
    tsplit<<<dim3(DD/32, DHH/32, 1), blk>>>(W_proj, wprojH, wprojL, DHH, DD, 0, 0);
    tsplit<<<dim3(DD/32, DD/32, 1), blk>>>(Wq, wqH, wqL, DD, DD, 0, 0);
    tsplit<<<dim3(DD/32, DD/32, 1), blk>>>(Wk, wkH, wkL, DD, DD, 0, 0);
    tsplit<<<dim3(DD/32, DD/32, 1), blk>>>(Wv, wvH, wvL, DD, DD, 0, 0);
    tsplit<<<dim3(4*DD/32, DD/32, 1), blk>>>(W_f1, wf1H, wf1L, DD, 4*DD, 0, 0);
    tsplit<<<dim3(DD/32, 4*DD/32, 1), blk>>>(W_f2, wf2H, wf2L, 4*DD, DD, 0, 0);

    // 1) input LN -> bf16 split (a)
    ln_kernel<<<MROWS, blk>>>(x, nullptr, ln_in_g, ln_in_b, nullptr, aH, aL);
    // 2) MLP up: relu -> big split
    gemm2<1,2><<<dim3(DHH/64, MROWS/128, 1), blk, GEMM_SMEM>>>(
        aH, aL, wmlpH, wmlpL, b_mlp, nullptr, bigH, bigL, MROWS, DHH, DD, 0, 0, 0);
    // 3) proj: clip -> f0 (fp32) + b split
    gemm2<2,3><<<dim3(DD/64, MROWS/128, 1), blk, GEMM_SMEM>>>(
        bigH, bigL, wprojH, wprojL, b_proj, f0, bH, bL, MROWS, DD, DHH, 0, 0, 0);
    // 4) q, k (bf16 split), v (fp32)
    gemm2<0,2><<<dim3(DD/64, MROWS/128, 1), blk, GEMM_SMEM>>>(
        bH, bL, wqH, wqL, bq, nullptr, qH, qL, MROWS, DD, DD, 0, 0, 0);
    gemm2<0,2><<<dim3(DD/64, MROWS/128, 1), blk, GEMM_SMEM>>>(
        bH, bL, wkH, wkL, bk, nullptr, kH, kL, MROWS, DD, DD, 0, 0, 0);
    gemm2<0,1><<<dim3(DD/64, MROWS/128, 1), blk, GEMM_SMEM>>>(
        bH, bL, wvH, wvL, bv, f2, nullptr, nullptr, MROWS, DD, DD, 0, 0, 0);
    // 5) v transpose+split per batch: [s][d] -> [d][s]
    tsplit<<<dim3(32, 32, BB), blk>>>(f2, vtH, vtL, SS, DD, SD, SD);
    // 6) scores = q @ k^T -> f1 (fp32), batched
    gemm2<0,1><<<dim3(SS/64, SS/128, BB), blk, GEMM_SMEM>>>(
        qH, qL, kH, kL, nullptr, f1, nullptr, nullptr, SS, SS, DD, SD, SD, SD);
    // 7) masked softmax -> probs split (a, reuse)
    softmax_split<<<BB * SS, blk>>>(f1, mask, scale, aH, aL);
    // 8) attn_out = probs @ v -> f3 (fp32), batched
    gemm2<0,1><<<dim3(DD/64, SS/128, BB), blk, GEMM_SMEM>>>(
        aH, aL, vtH, vtL, nullptr, f3, nullptr, nullptr, SS, DD, SS, SD, SD, SD);
    // 9) ln1(identity + attn) -> f4 (fp32) + b split (reuse)
    ln_kernel<<<MROWS, blk>>>(f0, f3, ln1_g, ln1_b, f4, bH, bL);
    // 10) FFN up: relu -> big split
    gemm2<1,2><<<dim3(4*DD/64, MROWS/128, 1), blk, GEMM_SMEM>>>(
        bH, bL, wf1H, wf1L, b_f1, nullptr, bigH, bigL, MROWS, 4*DD, DD, 0, 0, 0);
    // 11) FFN down -> f1 (fp32, reuse)
    gemm2<0,1><<<dim3(DD/64, MROWS/128, 1), blk, GEMM_SMEM>>>(
        bigH, bigL, wf2H, wf2L, b_f2, f1, nullptr, nullptr, MROWS, DD, 4*DD, 0, 0, 0);
    // 12) ln2(ln1_out + ffn) -> f2 (fp32, reuse)
    ln_kernel<<<MROWS, blk>>>(f4, f1, ln2_g, ln2_b, f2, nullptr, nullptr);
    // 13) output LN -> d_out
    ln_kernel<<<MROWS, blk>>>(f2, nullptr, lno_g, lno_b, out, nullptr, nullptr);
}

// round 8
// speedup vs baseline: 1.3531x; 1.3531x over previous
#include <cuda_runtime.h>
#include <cuda_bf16.h>
#include <cstdint>

#define BB   16
#define SS   1024
#define DD   1024
#define DHH  4096
#define MROWS (BB * SS)   // 16384

typedef __nv_bfloat16 bf16;

// ---------------------------------------------------------------------------
// Scratch (__device__ globals; no allocation allowed). ~1 GB total.
// ---------------------------------------------------------------------------
__device__ __align__(16) bf16 g_big_hi[MROWS * DHH];
__device__ __align__(16) bf16 g_big_lo[MROWS * DHH];
__device__ __align__(16) bf16 g_a_hi[MROWS * DD];
__device__ __align__(16) bf16 g_a_lo[MROWS * DD];
__device__ __align__(16) bf16 g_b_hi[MROWS * DD];
__device__ __align__(16) bf16 g_b_lo[MROWS * DD];
__device__ __align__(16) bf16 g_q_hi[MROWS * DD];
__device__ __align__(16) bf16 g_q_lo[MROWS * DD];
__device__ __align__(16) bf16 g_k_hi[MROWS * DD];
__device__ __align__(16) bf16 g_k_lo[MROWS * DD];
__device__ __align__(16) bf16 g_vt_hi[MROWS * DD];
__device__ __align__(16) bf16 g_vt_lo[MROWS * DD];
__device__ __align__(16) float g_f0[MROWS * DD];
__device__ __align__(16) float g_f1[MROWS * DD];
__device__ __align__(16) float g_f2[MROWS * DD];
__device__ __align__(16) float g_f3[MROWS * DD];
__device__ __align__(16) float g_f4[MROWS * DD];
__device__ __align__(16) bf16 g_wmlp_hi[DHH * DD];  __device__ __align__(16) bf16 g_wmlp_lo[DHH * DD];
__device__ __align__(16) bf16 g_wproj_hi[DD * DHH]; __device__ __align__(16) bf16 g_wproj_lo[DD * DHH];
__device__ __align__(16) bf16 g_wq_hi[DD * DD];     __device__ __align__(16) bf16 g_wq_lo[DD * DD];
__device__ __align__(16) bf16 g_wk_hi[DD * DD];     __device__ __align__(16) bf16 g_wk_lo[DD * DD];
__device__ __align__(16) bf16 g_wv_hi[DD * DD];     __device__ __align__(16) bf16 g_wv_lo[DD * DD];
__device__ __align__(16) bf16 g_wf1_hi[4*DD * DD];  __device__ __align__(16) bf16 g_wf1_lo[4*DD * DD];
__device__ __align__(16) bf16 g_wf2_hi[DD * 4*DD];  __device__ __align__(16) bf16 g_wf2_lo[DD * 4*DD];

// ---------------------------------------------------------------------------
// PTX helpers (sm_100 base ISA only: cp.async, ldmatrix, mma.sync)
// ---------------------------------------------------------------------------
__device__ __forceinline__ void cp16(bf16* s, const bf16* g) {
    uint32_t sa = (uint32_t)__cvta_generic_to_shared(s);
    asm volatile("cp.async.cg.shared.global [%0], [%1], 16;\n" :: "r"(sa), "l"(g));
}
__device__ __forceinline__ void ldm4(uint32_t* r, uint32_t addr) {
    asm volatile("ldmatrix.sync.aligned.m8n8.x4.shared.b16 {%0,%1,%2,%3}, [%4];\n"
                 : "=r"(r[0]), "=r"(r[1]), "=r"(r[2]), "=r"(r[3]) : "r"(addr));
}
__device__ __forceinline__ void mma16816(float* c, const uint32_t* a, const uint32_t* b) {
    asm volatile("mma.sync.aligned.m16n8k16.row.col.f32.bf16.bf16.f32 "
                 "{%0,%1,%2,%3}, {%4,%5,%6,%7}, {%8,%9}, {%0,%1,%2,%3};\n"
                 : "+f"(c[0]), "+f"(c[1]), "+f"(c[2]), "+f"(c[3])
                 : "r"(a[0]), "r"(a[1]), "r"(a[2]), "r"(a[3]), "r"(b[0]), "r"(b[1]));
}
__device__ __forceinline__ void split_bf16(float v, bf16& h, bf16& l) {
    h = __float2bfloat16(v);
    l = __float2bfloat16(v - __bfloat162float(h));
}

// ---------------------------------------------------------------------------
// bf16x3 GEMM: C[M,N] = (Ahi+Alo)[M,K] @ (Bhi+Blo)[N,K]^T (+bias, act)
// 128x128x32 tile, 256 threads, cp.async double buffer, mma.sync m16n8k16.
// OUTM bit0: write fp32 Cf; bit1: write bf16 split Chi/Clo.
// ACT: 0 = none, 1 = relu, 2 = clip(+-100)
// MAXB: __launch_bounds__ min-blocks (1 = round-3 baseline, 2 = occupancy probe)
// ---------------------------------------------------------------------------
#define GSTRIDE 40
#define GEMM_SMEM (2 * 4 * 128 * GSTRIDE * 2)   // 81920 B

template<int ACT, int OUTM, int MAXB>
__global__ __launch_bounds__(256, MAXB)
void gemm3(const bf16* __restrict__ Ahi, const bf16* __restrict__ Alo,
           const bf16* __restrict__ Bhi, const bf16* __restrict__ Blo,
           const float* __restrict__ bias,
           float* __restrict__ Cf, bf16* __restrict__ Chi, bf16* __restrict__ Clo,
           int M, int N, int K,
           long long sA, long long sB, long long sC)
{
    extern __shared__ bf16 sm[];
    const int tid = threadIdx.x;
    const int wid = tid >> 5, lane = tid & 31;
    const int wm = wid >> 1, wn = wid & 1;      // 4x2 warps -> 32x64 warp tile
    const long long z = blockIdx.z;
    Ahi += z * sA; Alo += z * sA; Bhi += z * sB; Blo += z * sB;
    const long long bM = (long long)blockIdx.y * 128;
    const long long bN = (long long)blockIdx.x * 128;

    float acc[2][8][4];
    #pragma unroll
    for (int mi = 0; mi < 2; mi++)
        #pragma unroll
        for (int ni = 0; ni < 8; ni++)
            #pragma unroll
            for (int j = 0; j < 4; j++) acc[mi][ni][j] = 0.f;

    const int cr = tid >> 2, cc = tid & 3;      // cp.async mapping
    const uint32_t smb = (uint32_t)__cvta_generic_to_shared(sm);

    auto load_stage = [&](int s, int k0) {
        const bf16* bases[4] = {Ahi, Alo, Bhi, Blo};
        #pragma unroll
        for (int t = 0; t < 4; t++) {
            long long ro = (t < 2) ? bM : bN;
            const bf16* bp = bases[t] + (ro + cr) * (long long)K + k0 + cc * 8;
            bf16* sp = sm + ((s * 4 + t) * 128 + cr) * GSTRIDE + cc * 8;
            cp16(sp, bp);
            cp16(sp + 64 * GSTRIDE, bp + 64LL * K);
        }
        asm volatile("cp.async.commit_group;\n" ::: "memory");
    };

    auto compute = [&](int s) {
        #pragma unroll
        for (int ks = 0; ks < 2; ks++) {
            const int lr = lane & 15;
            const int lc = ks * 16 + ((lane >> 4) << 3);
            uint32_t ah[2][4], al[2][4], bh[8][2], bl[8][2];
            #pragma unroll
            for (int mi = 0; mi < 2; mi++) {
                ldm4(ah[mi], smb + 2u * (((s*4 + 0) * 128 + wm*32 + mi*16 + lr) * GSTRIDE + lc));
                ldm4(al[mi], smb + 2u * (((s*4 + 1) * 128 + wm*32 + mi*16 + lr) * GSTRIDE + lc));
            }
            #pragma unroll
            for (int g = 0; g < 4; g++) {
                uint32_t r[4];
                ldm4(r, smb + 2u * (((s*4 + 2) * 128 + wn*64 + g*16 + lr) * GSTRIDE + lc));
                bh[g*2][0] = r[0]; bh[g*2+1][0] = r[1]; bh[g*2][1] = r[2]; bh[g*2+1][1] = r[3];
                ldm4(r, smb + 2u * (((s*4 + 3) * 128 + wn*64 + g*16 + lr) * GSTRIDE + lc));
                bl[g*2][0] = r[0]; bl[g*2+1][0] = r[1]; bl[g*2][1] = r[2]; bl[g*2+1][1] = r[3];
            }
            #pragma unroll
            for (int mi = 0; mi < 2; mi++)
                #pragma unroll
                for (int ni = 0; ni < 8; ni++)
                    mma16816(acc[mi][ni], ah[mi], bh[ni]);
            #pragma unroll
            for (int mi = 0; mi < 2; mi++)
                #pragma unroll
                for (int ni = 0; ni < 8; ni++)
                    mma16816(acc[mi][ni], ah[mi], bl[ni]);
            #pragma unroll
            for (int mi = 0; mi < 2; mi++)
                #pragma unroll
                for (int ni = 0; ni < 8; ni++)
                    mma16816(acc[mi][ni], al[mi], bh[ni]);
        }
    };

    const int niter = K >> 5;
    load_stage(0, 0);
    for (int i = 0; i < niter; i++) {
        asm volatile("cp.async.wait_group 0;\n" ::: "memory");
        __syncthreads();
        if (i + 1 < niter) load_stage((i + 1) & 1, (i + 1) << 5);
        compute(i & 1);
    }

    // epilogue
    const long long cb = z * sC;
    const int g4 = lane >> 2, l4 = lane & 3;
    #pragma unroll
    for (int mi = 0; mi < 2; mi++) {
        #pragma unroll
        for (int half = 0; half < 2; half++) {
            const long long row = bM + wm*32 + mi*16 + half*8 + g4;
            #pragma unroll
            for (int ni = 0; ni < 8; ni++) {
                const long long col = bN + wn*64 + ni*8 + l4*2;
                float v0 = acc[mi][ni][half*2 + 0];
                float v1 = acc[mi][ni][half*2 + 1];
                if (bias) { v0 += bias[col]; v1 += bias[col + 1]; }
                if (ACT == 1) { v0 = fmaxf(v0, 0.f); v1 = fmaxf(v1, 0.f); }
                if (ACT == 2) {
                    v0 = fminf(fmaxf(v0, -100.f), 100.f);
                    v1 = fminf(fmaxf(v1, -100.f), 100.f);
                }
                const long long idx = cb + row * N + col;
                if (OUTM & 1) *(float2*)(Cf + idx) = make_float2(v0, v1);
                if (OUTM & 2) {
                    bf16 h0, l0, h1, l1;
                    split_bf16(v0, h0, l0); split_bf16(v1, h1, l1);
                    *(__nv_bfloat162*)(Chi + idx) = __halves2bfloat162(h0, h1);
                    *(__nv_bfloat162*)(Clo + idx) = __halves2bfloat162(l0, l1);
                }
            }
        }
    }
}

// ---------------------------------------------------------------------------
// Transpose + split: in fp32 [R][C] (batched) -> out bf16 [C][R] hi/lo
// ---------------------------------------------------------------------------
__global__ __launch_bounds__(256)
void tsplit(const float* __restrict__ in, bf16* __restrict__ ohi, bf16* __restrict__ olo,
            int R, int C, long long sIn, long long sOut)
{
    __shared__ float t[32][33];
    in += blockIdx.z * sIn; ohi += blockIdx.z * sOut; olo += blockIdx.z * sOut;
    const int bx = blockIdx.x * 32, by = blockIdx.y * 32;
    const int tx = threadIdx.x & 31, ty = threadIdx.x >> 5;   // 32 x 8
    #pragma unroll
    for (int i = 0; i < 32; i += 8)
        t[ty + i][tx] = in[(long long)(by + ty + i) * C + bx + tx];
    __syncthreads();
    #pragma unroll
    for (int i = 0; i < 32; i += 8) {
        float v = t[tx][ty + i];
        bf16 h, l; split_bf16(v, h, l);
        const long long o = (long long)(bx + ty + i) * R + by + tx;
        ohi[o] = h; olo[o] = l;
    }
}

// ---------------------------------------------------------------------------
// LayerNorm over D=1024 (+optional residual); outputs fp32 and/or bf16 split.
// ---------------------------------------------------------------------------
__global__ __launch_bounds__(256)
void ln_kernel(const float* __restrict__ in, const float* __restrict__ res,
               const float* __restrict__ gam, const float* __restrict__ bet,
               float* __restrict__ outf, bf16* __restrict__ ohi, bf16* __restrict__ olo)
{
    __shared__ float sh[64];
    const long long row = blockIdx.x;
    const int t = threadIdx.x;

    float4 v = ((const float4*)(in + row * DD))[t];
    if (res) {
        float4 r = ((const float4*)(res + row * DD))[t];
        v.x += r.x; v.y += r.y; v.z += r.z; v.w += r.w;
    }
    float s  = v.x + v.y + v.z + v.w;
    float ss = v.x*v.x + v.y*v.y + v.z*v.z + v.w*v.w;
    const int lane = t & 31, wid = t >> 5;
    #pragma unroll
    for (int o = 16; o > 0; o >>= 1) {
        s  += __shfl_down_sync(0xffffffffu, s,  o);
        ss += __shfl_down_sync(0xffffffffu, ss, o);
    }
    if (lane == 0) { sh[wid] = s; sh[32 + wid] = ss; }
    __syncthreads();
    if (t == 0) {
        float ts = 0.f, tss = 0.f;
        #pragma unroll
        for (int i = 0; i < 8; i++) { ts += sh[i]; tss += sh[32 + i]; }
        float mean = ts * (1.f / DD);
        float var  = tss * (1.f / DD) - mean * mean;
        sh[0] = mean; sh[1] = rsqrtf(var + 1e-5f);
    }
    __syncthreads();
    const float mean = sh[0], inv = sh[1];

    float4 g4 = ((const float4*)gam)[t];
    float4 b4 = ((const float4*)bet)[t];
    float4 o;
    o.x = (v.x - mean) * inv * g4.x + b4.x;
    o.y = (v.y - mean) * inv * g4.y + b4.y;
    o.z = (v.z - mean) * inv * g4.z + b4.z;
    o.w = (v.w - mean) * inv * g4.w + b4.w;
    if (outf) ((float4*)(outf + row * DD))[t] = o;
    if (ohi) {
        bf16 h0,l0,h1,l1,h2,l2,h3,l3;
        split_bf16(o.x,h0,l0); split_bf16(o.y,h1,l1);
        split_bf16(o.z,h2,l2); split_bf16(o.w,h3,l3);
        __nv_bfloat162* ph = (__nv_bfloat162*)(ohi + row * DD);
        __nv_bfloat162* pl = (__nv_bfloat162*)(olo + row * DD);
        ph[t*2]   = __halves2bfloat162(h0, h1);
        ph[t*2+1] = __halves2bfloat162(h2, h3);
        pl[t*2]   = __halves2bfloat162(l0, l1);
        pl[t*2+1] = __halves2bfloat162(l2, l3);
    }
}

// ---------------------------------------------------------------------------
// Masked scaled softmax; reads fp32 scores, writes bf16 split probs.
// ---------------------------------------------------------------------------
__global__ __launch_bounds__(256)
void softmax_split(const float* __restrict__ scores, const int* __restrict__ mask,
                   const float* __restrict__ scale,
                   bf16* __restrict__ phi, bf16* __restrict__ plo)
{
    __shared__ float sh[16];
    const long long row = blockIdx.x;
    const int b = (int)(row >> 10);
    const int t = threadIdx.x;

    const float4 vin = ((const float4*)(scores + row * SS))[t];
    const int4 mm = ((const int4*)(mask + (long long)b * SS))[t];
    const float sc = scale[0];

    float4 v;
    v.x = mm.x ? vin.x * sc : -1e9f;
    v.y = mm.y ? vin.y * sc : -1e9f;
    v.z = mm.z ? vin.z * sc : -1e9f;
    v.w = mm.w ? vin.w * sc : -1e9f;

    float mx = fmaxf(fmaxf(v.x, v.y), fmaxf(v.z, v.w));
    const int lane = t & 31, wid = t >> 5;
    #pragma unroll
    for (int o = 16; o > 0; o >>= 1)
        mx = fmaxf(mx, __shfl_down_sync(0xffffffffu, mx, o));
    if (lane == 0) sh[wid] = mx;
    __syncthreads();
    if (t == 0) {
        float m = sh[0];
        #pragma unroll
        for (int i = 1; i < 8; i++) m = fmaxf(m, sh[i]);
        sh[8] = m;
    }
    __syncthreads();
    mx = sh[8];

    float4 e;
    e.x = expf(v.x - mx); e.y = expf(v.y - mx);
    e.z = expf(v.z - mx); e.w = expf(v.w - mx);
    float sum = e.x + e.y + e.z + e.w;
    #pragma unroll
    for (int o = 16; o > 0; o >>= 1)
        sum += __shfl_down_sync(0xffffffffu, sum, o);
    __syncthreads();
    if (lane == 0) sh[wid] = sum;
    __syncthreads();
    if (t == 0) {
        float sv = 0.f;
        #pragma unroll
        for (int i = 0; i < 8; i++) sv += sh[i];
        sh[9] = 1.f / sv;
    }
    __syncthreads();
    const float invs = sh[9];

    e.x *= invs; e.y *= invs; e.z *= invs; e.w *= invs;
    bf16 h0,l0,h1,l1,h2,l2,h3,l3;
    split_bf16(e.x,h0,l0); split_bf16(e.y,h1,l1);
    split_bf16(e.z,h2,l2); split_bf16(e.w,h3,l3);
    __nv_bfloat162* ph = (__nv_bfloat162*)(phi + row * SS);
    __nv_bfloat162* pl = (__nv_bfloat162*)(plo + row * SS);
    ph[t*2]   = __halves2bfloat162(h0, h1);
    ph[t*2+1] = __halves2bfloat162(h2, h3);
    pl[t*2]   = __halves2bfloat162(l0, l1);
    pl[t*2+1] = __halves2bfloat162(l2, l3);
}

// ---------------------------------------------------------------------------
// Launch. Order matters for ncu (-s 5 -c 1): launch index 5 must be the
// MLP-up gemm3 so the profile finally captures a GEMM, not a tsplit.
// ---------------------------------------------------------------------------
extern "C" void kernel_launch(void* const* d_in, const int* in_sizes, int n_in,
                              void* d_out, int out_size)
{
    const float* x       = (const float*)d_in[0];
    const int*   mask    = (const int*)  d_in[1];
    const float* ln_in_g = (const float*)d_in[2];
    const float* ln_in_b = (const float*)d_in[3];
    const float* W_mlp   = (const float*)d_in[4];
    const float* b_mlp   = (const float*)d_in[5];
    const float* W_proj  = (const float*)d_in[6];
    const float* b_proj  = (const float*)d_in[7];
    const float* scale   = (const float*)d_in[8];
    const float* Wq      = (const float*)d_in[9];
    const float* bq      = (const float*)d_in[10];
    const float* Wk      = (const float*)d_in[11];
    const float* bk      = (const float*)d_in[12];
    const float* Wv      = (const float*)d_in[13];
    const float* bv      = (const float*)d_in[14];
    const float* ln1_g   = (const float*)d_in[15];
    const float* ln1_b   = (const float*)d_in[16];
    const float* W_f1    = (const float*)d_in[17];
    const float* b_f1    = (const float*)d_in[18];
    const float* W_f2    = (const float*)d_in[19];
    const float* b_f2    = (const float*)d_in[20];
    const float* ln2_g   = (const float*)d_in[21];
    const float* ln2_b   = (const float*)d_in[22];
    const float* lno_g   = (const float*)d_in[23];
    const float* lno_b   = (const float*)d_in[24];
    float* out = (float*)d_out;

    bf16 *bigH,*bigL,*aH,*aL,*bH,*bL,*qH,*qL,*kH,*kL,*vtH,*vtL;
    bf16 *wmlpH,*wmlpL,*wprojH,*wprojL,*wqH,*wqL,*wkH,*wkL,*wvH,*wvL,*wf1H,*wf1L,*wf2H,*wf2L;
    float *f0,*f1,*f2,*f3,*f4;
    cudaGetSymbolAddress((void**)&bigH, g_big_hi); cudaGetSymbolAddress((void**)&bigL, g_big_lo);
    cudaGetSymbolAddress((void**)&aH, g_a_hi);     cudaGetSymbolAddress((void**)&aL, g_a_lo);
    cudaGetSymbolAddress((void**)&bH, g_b_hi);     cudaGetSymbolAddress((void**)&bL, g_b_lo);
    cudaGetSymbolAddress((void**)&qH, g_q_hi);     cudaGetSymbolAddress((void**)&qL, g_q_lo);
    cudaGetSymbolAddress((void**)&kH, g_k_hi);     cudaGetSymbolAddress((void**)&kL, g_k_lo);
    cudaGetSymbolAddress((void**)&vtH, g_vt_hi);   cudaGetSymbolAddress((void**)&vtL, g_vt_lo);
    cudaGetSymbolAddress((void**)&wmlpH, g_wmlp_hi);   cudaGetSymbolAddress((void**)&wmlpL, g_wmlp_lo);
    cudaGetSymbolAddress((void**)&wprojH, g_wproj_hi); cudaGetSymbolAddress((void**)&wprojL, g_wproj_lo);
    cudaGetSymbolAddress((void**)&wqH, g_wq_hi);   cudaGetSymbolAddress((void**)&wqL, g_wq_lo);
    cudaGetSymbolAddress((void**)&wkH, g_wk_hi);   cudaGetSymbolAddress((void**)&wkL, g_wk_lo);
    cudaGetSymbolAddress((void**)&wvH, g_wv_hi);   cudaGetSymbolAddress((void**)&wvL, g_wv_lo);
    cudaGetSymbolAddress((void**)&wf1H, g_wf1_hi); cudaGetSymbolAddress((void**)&wf1L, g_wf1_lo);
    cudaGetSymbolAddress((void**)&wf2H, g_wf2_hi); cudaGetSymbolAddress((void**)&wf2L, g_wf2_lo);
    cudaGetSymbolAddress((void**)&f0, g_f0); cudaGetSymbolAddress((void**)&f1, g_f1);
    cudaGetSymbolAddress((void**)&f2, g_f2); cudaGetSymbolAddress((void**)&f3, g_f3);
    cudaGetSymbolAddress((void**)&f4, g_f4);

    cudaFuncSetAttribute(gemm3<0,1,1>, cudaFuncAttributeMaxDynamicSharedMemorySize, GEMM_SMEM);
    cudaFuncSetAttribute(gemm3<0,2,1>, cudaFuncAttributeMaxDynamicSharedMemorySize, GEMM_SMEM);
    cudaFuncSetAttribute(gemm3<1,2,1>, cudaFuncAttributeMaxDynamicSharedMemorySize, GEMM_SMEM);
    cudaFuncSetAttribute(gemm3<2,3,1>, cudaFuncAttributeMaxDynamicSharedMemorySize, GEMM_SMEM);
    cudaFuncSetAttribute(gemm3<1,2,2>, cudaFuncAttributeMaxDynamicSharedMemorySize, GEMM_SMEM);

    const dim3 blk(256);
    const long long SD = (long long)SS * DD;   // 1M: per-batch stride

    // Launches 0-4: exactly five before the first GEMM (ncu -s 5 lands on it)
    tsplit<<<dim3(DHH/32, DD/32, 1), blk>>>(W_mlp, wmlpH, wmlpL, DD, DHH, 0, 0);    // 0
    tsplit<<<dim3(DD/32, DHH/32, 1), blk>>>(W_proj, wprojH, wprojL, DHH, DD, 0, 0); // 1
    tsplit<<<dim3(DD/32, DD/32, 1), blk>>>(Wq, wqH, wqL, DD, DD, 0, 0);             // 2
    tsplit<<<dim3(DD/32, DD/32, 1), blk>>>(Wk, wkH, wkL, DD, DD, 0, 0);             // 3
    ln_kernel<<<MROWS, blk>>>(x, nullptr, ln_in_g, ln_in_b, nullptr, aH, aL);       // 4

    // Launch 5: MLP up (PROFILED)
    gemm3<1,2,1><<<dim3(DHH/128, MROWS/128, 1), blk, GEMM_SMEM>>>(
        aH, aL, wmlpH, wmlpL, b_mlp, nullptr, bigH, bigL, MROWS, DHH, DD, 0, 0, 0);

    // Deferred weight splits (needed only later in the pipeline)
    tsplit<<<dim3(DD/32, DD/32, 1), blk>>>(Wv, wvH, wvL, DD, DD, 0, 0);
    tsplit<<<dim3(4*DD/32, DD/32, 1), blk>>>(W_f1, wf1H, wf1L, DD, 4*DD, 0, 0);
    tsplit<<<dim3(DD/32, 4*DD/32, 1), blk>>>(W_f2, wf2H, wf2L, 4*DD, DD, 0, 0);

    // proj: clip -> f0 (fp32) + b split
    gemm3<2,3,1><<<dim3(DD/128, MROWS/128, 1), blk, GEMM_SMEM>>>(
        bigH, bigL, wprojH, wprojL, b_proj, f0, bH, bL, MROWS, DD, DHH, 0, 0, 0);
    // q, k (bf16 split), v (fp32)
    gemm3<0,2,1><<<dim3(DD/128, MROWS/128, 1), blk, GEMM_SMEM>>>(
        bH, bL, wqH, wqL, bq, nullptr, qH, qL, MROWS, DD, DD, 0, 0, 0);
    gemm3<0,2,1><<<dim3(DD/128, MROWS/128, 1), blk, GEMM_SMEM>>>(
        bH, bL, wkH, wkL, bk, nullptr, kH, kL, MROWS, DD, DD, 0, 0, 0);
    gemm3<0,1,1><<<dim3(DD/128, MROWS/128, 1), blk, GEMM_SMEM>>>(
        bH, bL, wvH, wvL, bv, f2, nullptr, nullptr, MROWS, DD, DD, 0, 0, 0);
    // v transpose+split per batch: [s][d] -> [d][s]
    tsplit<<<dim3(32, 32, BB), blk>>>(f2, vtH, vtL, SS, DD, SD, SD);
    // scores = q @ k^T -> f1 (fp32), batched
    gemm3<0,1,1><<<dim3(SS/128, SS/128, BB), blk, GEMM_SMEM>>>(
        qH, qL, kH, kL, nullptr, f1, nullptr, nullptr, SS, SS, DD, SD, SD, SD);
    // masked softmax -> probs split (a, reuse)
    softmax_split<<<BB * SS, blk>>>(f1, mask, scale, aH, aL);
    // attn_out = probs @ v -> f3 (fp32), batched
    gemm3<0,1,1><<<dim3(DD/128, SS/128, BB), blk, GEMM_SMEM>>>(
        aH, aL, vtH, vtL, nullptr, f3, nullptr, nullptr, SS, DD, SS, SD, SD, SD);
    // ln1(identity + attn) -> f4 (fp32) + b split (reuse)
    ln_kernel<<<MROWS, blk>>>(f0, f3, ln1_g, ln1_b, f4, bH, bL);
    // FFN up: relu -> big split  [A/B probe: 2-CTA/SM launch-bounds variant]
    gemm3<1,2,2><<<dim3(4*DD/128, MROWS/128, 1), blk, GEMM_SMEM>>>(
        bH, bL, wf1H, wf1L, b_f1, nullptr, bigH, bigL, MROWS, 4*DD, DD, 0, 0, 0);
    // FFN down -> f1 (fp32, reuse)
    gemm3<0,1,1><<<dim3(DD/128, MROWS/128, 1), blk, GEMM_SMEM>>>(
        bigH, bigL, wf2H, wf2L, b_f2, f1, nullptr, nullptr, MROWS, DD, 4*DD, 0, 0, 0);
    // ln2(ln1_out + ffn) -> f2 (fp32, reuse)
    ln_kernel<<<MROWS, blk>>>(f4, f1, ln2_g, ln2_b, f2, nullptr, nullptr);
    // output LN -> d_out
    ln_kernel<<<MROWS, blk>>>(f2, nullptr, lno_g, lno_b, out, nullptr, nullptr);
}